// round 3
// baseline (speedup 1.0000x reference)
#include <cuda_runtime.h>
#include <cuda_bf16.h>
#include <math.h>

// Problem constants
#define Bz 4
#define Lz 2048
#define Dm 1024
#define Hh 16
#define HD 64
#define Mrows (Bz*Lz)   // 8192
#define EPSLN 1e-5f

// Scratch (static device globals — allocation-free)
__device__ float g_q[(size_t)Mrows * Dm];
__device__ float g_k[(size_t)Mrows * Dm];
__device__ float g_v[(size_t)Mrows * Dm];
__device__ float g_attn[(size_t)Mrows * Dm];
__device__ float g_proj[(size_t)Mrows * Dm];

// ---------------------------------------------------------------------------
// GEMM: C[M,N] = A[M,K] @ W[K,N] + bias[N]
// 128x128 block tile, BK=16, 256 threads, 8x8 per thread (strided mapping)
// ---------------------------------------------------------------------------
#define BM 128
#define BN 128
#define BKg 16

__global__ __launch_bounds__(256, 2)
void gemm_bias(const float* __restrict__ A, const float* __restrict__ Bw,
               const float* __restrict__ bias, float* __restrict__ C,
               int Md, int Nd, int Kd) {
    __shared__ float As[BKg][BM];
    __shared__ float Bs[BKg][BN];

    const int tid = threadIdx.x;
    const int tx = tid & 15;
    const int ty = tid >> 4;
    const int m0 = blockIdx.y * BM;
    const int n0 = blockIdx.x * BN;

    float acc[8][8];
#pragma unroll
    for (int i = 0; i < 8; i++)
#pragma unroll
        for (int j = 0; j < 8; j++) acc[i][j] = 0.f;

    for (int k0 = 0; k0 < Kd; k0 += BKg) {
        // Load A tile (128 x 16) as float4, store transposed As[k][m]
#pragma unroll
        for (int it = 0; it < 2; it++) {
            int f = tid + it * 256;          // 0..511
            int m = f >> 2;                  // 0..127
            int kc = (f & 3) << 2;           // 0,4,8,12
            float4 v = *(const float4*)&A[(size_t)(m0 + m) * Kd + k0 + kc];
            As[kc + 0][m] = v.x;
            As[kc + 1][m] = v.y;
            As[kc + 2][m] = v.z;
            As[kc + 3][m] = v.w;
        }
        // Load B tile (16 x 128) as float4 directly
#pragma unroll
        for (int it = 0; it < 2; it++) {
            int f = tid + it * 256;
            int k = f >> 5;                  // 0..15
            int c = (f & 31) << 2;           // 0..124
            *(float4*)&Bs[k][c] = *(const float4*)&Bw[(size_t)(k0 + k) * Nd + n0 + c];
        }
        __syncthreads();

#pragma unroll
        for (int k = 0; k < BKg; k++) {
            float a[8], b[8];
#pragma unroll
            for (int i = 0; i < 8; i++) a[i] = As[k][ty + 16 * i];
#pragma unroll
            for (int j = 0; j < 8; j++) b[j] = Bs[k][tx + 16 * j];
#pragma unroll
            for (int i = 0; i < 8; i++)
#pragma unroll
                for (int j = 0; j < 8; j++) acc[i][j] += a[i] * b[j];
        }
        __syncthreads();
    }

#pragma unroll
    for (int i = 0; i < 8; i++) {
        int m = m0 + ty + 16 * i;
#pragma unroll
        for (int j = 0; j < 8; j++) {
            int n = n0 + tx + 16 * j;
            C[(size_t)m * Nd + n] = acc[i][j] + bias[n];
        }
    }
}

// ---------------------------------------------------------------------------
// Flash-attention (fp32, online softmax). One CTA per (b, h, 64-row q-tile).
// Tiles: Q 64x64 (persistent), K/V share one 64x64 buffer, P 64x64.
// All smem tiles use row stride 65 (diagonal bank mapping -> conflict-free).
// 256 threads: 16x16 grid, each thread 4x4 with strided mapping
// (i = ty + 16*ii, j = tx + 16*jj).
// ---------------------------------------------------------------------------
#define TS 65   // padded row stride

__global__ __launch_bounds__(256, 2)
void attn_kernel(const float* __restrict__ Q, const float* __restrict__ K,
                 const float* __restrict__ V, float* __restrict__ O) {
    extern __shared__ float sm[];
    float* Qs  = sm;                 // [64][65]
    float* KVs = sm + 64 * TS;       // [64][65]
    float* Ps  = sm + 2 * 64 * TS;   // [64][65]

    const int tid = threadIdx.x;
    const int tx = tid & 15;
    const int ty = tid >> 4;
    const int q0 = blockIdx.x * 64;
    const int h  = blockIdx.y;
    const int b  = blockIdx.z;
    const size_t base = (size_t)b * Lz * Dm + (size_t)h * HD;

    // Load Q tile, pre-scaled by 1/sqrt(HD) = 0.125
#pragma unroll
    for (int it = 0; it < 4; it++) {
        int f = tid + it * 256;          // 0..1023
        int r = f >> 4;                  // 0..63
        int c = (f & 15) << 2;           // 0..60
        float4 v = *(const float4*)&Q[base + (size_t)(q0 + r) * Dm + c];
        Qs[r * TS + c + 0] = v.x * 0.125f;
        Qs[r * TS + c + 1] = v.y * 0.125f;
        Qs[r * TS + c + 2] = v.z * 0.125f;
        Qs[r * TS + c + 3] = v.w * 0.125f;
    }

    float m_run[4], l_run[4];
    float o_acc[4][4];
#pragma unroll
    for (int i = 0; i < 4; i++) {
        m_run[i] = -1e30f;
        l_run[i] = 0.f;
#pragma unroll
        for (int j = 0; j < 4; j++) o_acc[i][j] = 0.f;
    }
    __syncthreads();

    for (int kt = 0; kt < Lz / 64; kt++) {
        const int k0 = kt * 64;
        // Load K tile
#pragma unroll
        for (int it = 0; it < 4; it++) {
            int f = tid + it * 256;
            int r = f >> 4;
            int c = (f & 15) << 2;
            float4 v = *(const float4*)&K[base + (size_t)(k0 + r) * Dm + c];
            KVs[r * TS + c + 0] = v.x;
            KVs[r * TS + c + 1] = v.y;
            KVs[r * TS + c + 2] = v.z;
            KVs[r * TS + c + 3] = v.w;
        }
        __syncthreads();

        // S = Qs @ KVs^T  (both stored [row][d])
        float s[4][4];
#pragma unroll
        for (int i = 0; i < 4; i++)
#pragma unroll
            for (int j = 0; j < 4; j++) s[i][j] = 0.f;

#pragma unroll 8
        for (int d = 0; d < 64; d++) {
            float a[4], bb[4];
#pragma unroll
            for (int i = 0; i < 4; i++) a[i] = Qs[(ty + 16 * i) * TS + d];
#pragma unroll
            for (int j = 0; j < 4; j++) bb[j] = KVs[(tx + 16 * j) * TS + d];
#pragma unroll
            for (int i = 0; i < 4; i++)
#pragma unroll
                for (int j = 0; j < 4; j++) s[i][j] += a[i] * bb[j];
        }
        __syncthreads();   // done reading K

        // Load V tile into the same buffer
#pragma unroll
        for (int it = 0; it < 4; it++) {
            int f = tid + it * 256;
            int r = f >> 4;
            int c = (f & 15) << 2;
            float4 v = *(const float4*)&V[base + (size_t)(k0 + r) * Dm + c];
            KVs[r * TS + c + 0] = v.x;
            KVs[r * TS + c + 1] = v.y;
            KVs[r * TS + c + 2] = v.z;
            KVs[r * TS + c + 3] = v.w;
        }

        // Online softmax update (registers only; row stats replicated per tx)
#pragma unroll
        for (int i = 0; i < 4; i++) {
            float mx = s[i][0];
#pragma unroll
            for (int j = 1; j < 4; j++) mx = fmaxf(mx, s[i][j]);
#pragma unroll
            for (int off = 8; off > 0; off >>= 1)
                mx = fmaxf(mx, __shfl_xor_sync(0xffffffffu, mx, off, 16));
            float mnew = fmaxf(m_run[i], mx);
            float sum = 0.f;
#pragma unroll
            for (int j = 0; j < 4; j++) {
                float p = __expf(s[i][j] - mnew);
                s[i][j] = p;
                sum += p;
            }
#pragma unroll
            for (int off = 8; off > 0; off >>= 1)
                sum += __shfl_xor_sync(0xffffffffu, sum, off, 16);
            float scale = __expf(m_run[i] - mnew);
            l_run[i] = l_run[i] * scale + sum;
            m_run[i] = mnew;
#pragma unroll
            for (int j = 0; j < 4; j++) o_acc[i][j] *= scale;
        }

        // Write P tile
#pragma unroll
        for (int i = 0; i < 4; i++)
#pragma unroll
            for (int j = 0; j < 4; j++)
                Ps[(ty + 16 * i) * TS + tx + 16 * j] = s[i][j];
        __syncthreads();   // V + P visible

        // O += P @ V
#pragma unroll 8
        for (int k = 0; k < 64; k++) {
            float a[4], bb[4];
#pragma unroll
            for (int i = 0; i < 4; i++) a[i] = Ps[(ty + 16 * i) * TS + k];
#pragma unroll
            for (int j = 0; j < 4; j++) bb[j] = KVs[k * TS + tx + 16 * j];
#pragma unroll
            for (int i = 0; i < 4; i++)
#pragma unroll
                for (int j = 0; j < 4; j++) o_acc[i][j] += a[i] * bb[j];
        }
        __syncthreads();   // done with KVs/Ps before next iteration
    }

    // Epilogue: divide by row sums, write out
#pragma unroll
    for (int i = 0; i < 4; i++) {
        float inv = 1.0f / l_run[i];
        int r = q0 + ty + 16 * i;
#pragma unroll
        for (int j = 0; j < 4; j++)
            O[base + (size_t)r * Dm + tx + 16 * j] = o_acc[i][j] * inv;
    }
}

// ---------------------------------------------------------------------------
// Residual + LayerNorm: out = LN(x + proj) * gamma + beta
// One CTA per row of 1024, 256 threads, 4 elements per thread
// ---------------------------------------------------------------------------
__global__ __launch_bounds__(256)
void resid_ln(const float* __restrict__ x, const float* __restrict__ proj,
              const float* __restrict__ gamma, const float* __restrict__ beta,
              float* __restrict__ out) {
    __shared__ float red1[8];
    __shared__ float red2[8];
    const int row = blockIdx.x;
    const int t = threadIdx.x;
    const float* xr = x + (size_t)row * Dm;
    const float* pr = proj + (size_t)row * Dm;
    float* outr = out + (size_t)row * Dm;

    float v[4];
    float s = 0.f;
#pragma unroll
    for (int i = 0; i < 4; i++) {
        int c = t + 256 * i;
        v[i] = xr[c] + pr[c];
        s += v[i];
    }
#pragma unroll
    for (int off = 16; off > 0; off >>= 1) s += __shfl_xor_sync(~0u, s, off);
    if ((t & 31) == 0) red1[t >> 5] = s;
    __syncthreads();
    float mu = 0.f;
#pragma unroll
    for (int i = 0; i < 8; i++) mu += red1[i];
    mu *= (1.0f / Dm);

    float vs = 0.f;
#pragma unroll
    for (int i = 0; i < 4; i++) {
        float d = v[i] - mu;
        vs += d * d;
    }
#pragma unroll
    for (int off = 16; off > 0; off >>= 1) vs += __shfl_xor_sync(~0u, vs, off);
    if ((t & 31) == 0) red2[t >> 5] = vs;
    __syncthreads();
    float var = 0.f;
#pragma unroll
    for (int i = 0; i < 8; i++) var += red2[i];
    var *= (1.0f / Dm);
    float rstd = rsqrtf(var + EPSLN);

#pragma unroll
    for (int i = 0; i < 4; i++) {
        int c = t + 256 * i;
        outr[c] = (v[i] - mu) * rstd * gamma[c] + beta[c];
    }
}

// ---------------------------------------------------------------------------
extern "C" void kernel_launch(void* const* d_in, const int* in_sizes, int n_in,
                              void* d_out, int out_size) {
    const float* x     = (const float*)d_in[0];
    const float* Wq    = (const float*)d_in[1];
    const float* bq    = (const float*)d_in[2];
    const float* Wk    = (const float*)d_in[3];
    const float* bk    = (const float*)d_in[4];
    const float* Wv    = (const float*)d_in[5];
    const float* bv    = (const float*)d_in[6];
    const float* Wo    = (const float*)d_in[7];
    const float* bo    = (const float*)d_in[8];
    const float* gamma = (const float*)d_in[9];
    const float* beta  = (const float*)d_in[10];
    float* out = (float*)d_out;

    float *q, *k, *v, *attn, *proj;
    cudaGetSymbolAddress((void**)&q,    g_q);
    cudaGetSymbolAddress((void**)&k,    g_k);
    cudaGetSymbolAddress((void**)&v,    g_v);
    cudaGetSymbolAddress((void**)&attn, g_attn);
    cudaGetSymbolAddress((void**)&proj, g_proj);

    const int attn_smem = 3 * 64 * TS * (int)sizeof(float);   // 49,920 B
    cudaFuncSetAttribute(attn_kernel, cudaFuncAttributeMaxDynamicSharedMemorySize,
                         attn_smem);

    dim3 ggrid(Dm / BN, Mrows / BM);   // (8, 64)
    gemm_bias<<<ggrid, 256>>>(x, Wq, bq, q, Mrows, Dm, Dm);
    gemm_bias<<<ggrid, 256>>>(x, Wk, bk, k, Mrows, Dm, Dm);
    gemm_bias<<<ggrid, 256>>>(x, Wv, bv, v, Mrows, Dm, Dm);

    dim3 agrid(Lz / 64, Hh, Bz);       // (32, 16, 4)
    attn_kernel<<<agrid, 256, attn_smem>>>(q, k, v, attn);

    gemm_bias<<<ggrid, 256>>>(attn, Wo, bo, proj, Mrows, Dm, Dm);

    resid_ln<<<Mrows, 256>>>(x, proj, gamma, beta, out);
}

// round 6
// speedup vs baseline: 2.8965x; 2.8965x over previous
#include <cuda_runtime.h>
#include <cuda_bf16.h>
#include <math.h>

// Problem constants
#define Bz 4
#define Lz 2048
#define Dm 1024
#define Hh 16
#define HD 64
#define Mrows (Bz*Lz)   // 8192
#define EPSLN 1e-5f

// Scratch (static device globals — allocation-free)
__device__ float g_q[(size_t)Mrows * Dm];
__device__ float g_k[(size_t)Mrows * Dm];
__device__ float g_v[(size_t)Mrows * Dm];
__device__ float g_attn[(size_t)Mrows * Dm];
__device__ float g_proj[(size_t)Mrows * Dm];

// ---------------------------------------------------------------------------
// tf32 helpers
// ---------------------------------------------------------------------------
__device__ __forceinline__ unsigned f2tf(float x) {
    unsigned u;
    asm("cvt.rna.tf32.f32 %0, %1;" : "=r"(u) : "f"(x));
    return u;
}

// D += A*B, m16n8k8, A row-major (tf32), B col-major (tf32), fp32 accum
__device__ __forceinline__ void mma_tf32(float c[4], const unsigned a[4],
                                         const unsigned b[2]) {
    asm volatile(
        "mma.sync.aligned.m16n8k8.row.col.f32.tf32.tf32.f32 "
        "{%0,%1,%2,%3},{%4,%5,%6,%7},{%8,%9},{%0,%1,%2,%3};"
        : "+f"(c[0]), "+f"(c[1]), "+f"(c[2]), "+f"(c[3])
        : "r"(a[0]), "r"(a[1]), "r"(a[2]), "r"(a[3]), "r"(b[0]), "r"(b[1]));
}

// ---------------------------------------------------------------------------
// GEMM: C[M,N] = A[M,K] @ W[K,N] + bias[N]   (M=8192, N=K=1024)
// CTA 128x128, BK=32, 8 warps (2x4 grid of 64x32 warp tiles), tf32 mma.
// Smem XOR swizzles keep all fragment LDS conflict-free.
// ---------------------------------------------------------------------------
#define SWZA(k) (((k)&3) ^ (((k)>>2)&3))

__global__ __launch_bounds__(256, 2)
void gemm_tc(const float* __restrict__ A, const float* __restrict__ Bw,
             const float* __restrict__ bias, float* __restrict__ C) {
    __shared__ unsigned As[32][128];   // [k][m ^ (SWZA(k)<<3)]
    __shared__ unsigned Bs[32][128];   // [k][n ^ ((k&3)<<3)]

    const int tid = threadIdx.x;
    const int lane = tid & 31;
    const int warp = tid >> 5;
    const int gid = lane >> 2;   // 0..7
    const int tig = lane & 3;    // 0..3
    const int wm = (warp >> 2) * 64;   // 0 or 64
    const int wn = (warp & 3) * 32;    // 0,32,64,96
    const int m0 = blockIdx.y * 128;
    const int n0 = blockIdx.x * 128;

    float c[4][4][4];
#pragma unroll
    for (int mt = 0; mt < 4; mt++)
#pragma unroll
        for (int nt = 0; nt < 4; nt++)
#pragma unroll
            for (int r = 0; r < 4; r++) c[mt][nt][r] = 0.f;

    for (int k0 = 0; k0 < Dm; k0 += 32) {
        // Load A tile 128x32 (transposed into As[k][m], swizzled)
#pragma unroll
        for (int it = 0; it < 4; it++) {
            int f = tid + it * 256;          // 0..1023
            int m = f >> 3;                  // 0..127
            int kc = (f & 7) << 2;           // 0..28
            float4 v = *(const float4*)&A[(size_t)(m0 + m) * Dm + k0 + kc];
            As[kc + 0][m ^ (SWZA(kc + 0) << 3)] = f2tf(v.x);
            As[kc + 1][m ^ (SWZA(kc + 1) << 3)] = f2tf(v.y);
            As[kc + 2][m ^ (SWZA(kc + 2) << 3)] = f2tf(v.z);
            As[kc + 3][m ^ (SWZA(kc + 3) << 3)] = f2tf(v.w);
        }
        // Load B tile 32x128 (swizzled, contiguous uint4 stores)
#pragma unroll
        for (int it = 0; it < 4; it++) {
            int f = tid + it * 256;
            int r = f >> 5;                  // 0..31
            int cc = (f & 31) << 2;          // 0..124
            float4 v = *(const float4*)&Bw[(size_t)(k0 + r) * Dm + n0 + cc];
            int pc = cc ^ ((r & 3) << 3);    // xor bits >=3, float4 stays contiguous
            uint4 u;
            u.x = f2tf(v.x); u.y = f2tf(v.y); u.z = f2tf(v.z); u.w = f2tf(v.w);
            *(uint4*)&Bs[r][pc] = u;
        }
        __syncthreads();

#pragma unroll
        for (int ks = 0; ks < 4; ks++) {
            const int kk = ks * 8;
            unsigned af[4][4], bf[4][2];
            const int kA = kk + tig;
            const int s1 = SWZA(kA) << 3;
            const int s2 = SWZA(kA + 4) << 3;
#pragma unroll
            for (int mt = 0; mt < 4; mt++) {
                int m = wm + 16 * mt + gid;
                af[mt][0] = As[kA][m ^ s1];
                af[mt][1] = As[kA][(m + 8) ^ s1];
                af[mt][2] = As[kA + 4][m ^ s2];
                af[mt][3] = As[kA + 4][(m + 8) ^ s2];
            }
#pragma unroll
            for (int nt = 0; nt < 4; nt++) {
                int n = wn + 8 * nt + gid;
                bf[nt][0] = Bs[kA][n ^ ((kA & 3) << 3)];
                bf[nt][1] = Bs[kA + 4][n ^ (((kA + 4) & 3) << 3)];
            }
#pragma unroll
            for (int mt = 0; mt < 4; mt++)
#pragma unroll
                for (int nt = 0; nt < 4; nt++)
                    mma_tf32(c[mt][nt], af[mt], bf[nt]);
        }
        __syncthreads();
    }

    // Epilogue: C layout c0,c1 = (row gid, cols 2tig,2tig+1); c2,c3 = row gid+8
#pragma unroll
    for (int mt = 0; mt < 4; mt++) {
        int m = m0 + wm + 16 * mt + gid;
#pragma unroll
        for (int nt = 0; nt < 4; nt++) {
            int n = n0 + wn + 8 * nt + 2 * tig;
            float2 bb = *(const float2*)&bias[n];
            float2 v0 = make_float2(c[mt][nt][0] + bb.x, c[mt][nt][1] + bb.y);
            float2 v1 = make_float2(c[mt][nt][2] + bb.x, c[mt][nt][3] + bb.y);
            *(float2*)&C[(size_t)m * Dm + n] = v0;
            *(float2*)&C[(size_t)(m + 8) * Dm + n] = v1;
        }
    }
}

// ---------------------------------------------------------------------------
// Flash attention on tensor cores (tf32). One CTA per (b, h, 64-q-row tile).
// 4 warps, each owns 16 query rows. Q fragments live in registers.
// KV smem swizzle: bank bits {d0, d1, d2^k2, d3^k0, d4^k1} — conflict-free for
// BOTH the S-phase (K^T) and PV-phase (V) B-fragment patterns.
// ---------------------------------------------------------------------------
__device__ __forceinline__ int kvswz(int key, int d) {
    return d ^ (((key >> 2) & 1) << 2) ^ ((key & 1) << 3) ^ (((key >> 1) & 1) << 4);
}

__global__ __launch_bounds__(128, 2)
void attn_tc(const float* __restrict__ Q, const float* __restrict__ K,
             const float* __restrict__ V, float* __restrict__ O) {
    __shared__ unsigned KVs[64][64];   // K then V tiles, kvswz layout
    __shared__ unsigned Ps[64][64];    // Q staging, then P; [row][d ^ ((row&7)<<2)]

    const int tid = threadIdx.x;
    const int lane = tid & 31;
    const int warp = tid >> 5;
    const int gid = lane >> 2;
    const int tig = lane & 3;
    const int q0 = blockIdx.x * 64;
    const int h = blockIdx.y;
    const int b = blockIdx.z;
    const size_t base = (size_t)b * Lz * Dm + (size_t)h * HD;

    // Stage Q (scaled by 1/8, tf32-rounded) into Ps
#pragma unroll
    for (int it = 0; it < 8; it++) {
        int f = tid + it * 128;
        int r = f >> 4;                  // 0..63
        int cc = (f & 15) << 2;          // 0..60
        float4 v = *(const float4*)&Q[base + (size_t)(q0 + r) * Dm + cc];
        int pc = cc ^ ((r & 7) << 2);    // bits 2..4 xor, float4 contiguous
        uint4 u;
        u.x = f2tf(v.x * 0.125f); u.y = f2tf(v.y * 0.125f);
        u.z = f2tf(v.z * 0.125f); u.w = f2tf(v.w * 0.125f);
        *(uint4*)&Ps[r][pc] = u;
    }
    __syncthreads();

    // Pull this warp's Q fragments into registers (rows warp*16+gid, +8)
    unsigned qf[8][4];
    {
        const int r0 = warp * 16 + gid;
        const int r1 = r0 + 8;
        const int sw0 = (r0 & 7) << 2;
        const int sw1 = (r1 & 7) << 2;
#pragma unroll
        for (int ks = 0; ks < 8; ks++) {
            int d0 = ks * 8 + tig;
            qf[ks][0] = Ps[r0][d0 ^ sw0];
            qf[ks][1] = Ps[r1][d0 ^ sw1];
            qf[ks][2] = Ps[r0][(d0 + 4) ^ sw0];
            qf[ks][3] = Ps[r1][(d0 + 4) ^ sw1];
        }
    }
    __syncthreads();   // Ps now free for P tiles

    float o[8][4];
#pragma unroll
    for (int nt = 0; nt < 8; nt++)
#pragma unroll
        for (int r = 0; r < 4; r++) o[nt][r] = 0.f;
    float mrun[2] = {-1e30f, -1e30f};
    float lrun[2] = {0.f, 0.f};

    for (int kt = 0; kt < Lz / 64; kt++) {
        const int k0t = kt * 64;

        // Load K tile
#pragma unroll
        for (int it = 0; it < 8; it++) {
            int f = tid + it * 128;
            int r = f >> 4, cc = (f & 15) << 2;
            float4 v = *(const float4*)&K[base + (size_t)(k0t + r) * Dm + cc];
            int pc = kvswz(r, cc);
            uint4 u;
            u.x = f2tf(v.x); u.y = f2tf(v.y); u.z = f2tf(v.z); u.w = f2tf(v.w);
            *(uint4*)&KVs[r][pc] = u;
        }
        __syncthreads();

        // S = Q @ K^T   (B[k=d][n=key] = K[key][d])
        float s[8][4];
#pragma unroll
        for (int nt = 0; nt < 8; nt++)
#pragma unroll
            for (int r = 0; r < 4; r++) s[nt][r] = 0.f;

#pragma unroll
        for (int ks = 0; ks < 8; ks++) {
            const int d0 = ks * 8 + tig;
#pragma unroll
            for (int nt = 0; nt < 8; nt++) {
                int key = nt * 8 + gid;
                unsigned bf[2];
                bf[0] = KVs[key][kvswz(key, d0)];
                bf[1] = KVs[key][kvswz(key, d0 + 4)];
                mma_tf32(s[nt], qf[ks], bf);
            }
        }
        __syncthreads();   // done reading K

        // Load V tile into the same buffer
#pragma unroll
        for (int it = 0; it < 8; it++) {
            int f = tid + it * 128;
            int r = f >> 4, cc = (f & 15) << 2;
            float4 v = *(const float4*)&V[base + (size_t)(k0t + r) * Dm + cc];
            int pc = kvswz(r, cc);
            uint4 u;
            u.x = f2tf(v.x); u.y = f2tf(v.y); u.z = f2tf(v.z); u.w = f2tf(v.w);
            *(uint4*)&KVs[r][pc] = u;
        }

        // Online softmax on register S (rows gid -> regs 0,1; gid+8 -> regs 2,3)
#pragma unroll
        for (int r = 0; r < 2; r++) {
            float mx = mrun[r];
#pragma unroll
            for (int nt = 0; nt < 8; nt++) {
                mx = fmaxf(mx, s[nt][2 * r]);
                mx = fmaxf(mx, s[nt][2 * r + 1]);
            }
            mx = fmaxf(mx, __shfl_xor_sync(0xffffffffu, mx, 1));
            mx = fmaxf(mx, __shfl_xor_sync(0xffffffffu, mx, 2));
            float sumv = 0.f;
#pragma unroll
            for (int nt = 0; nt < 8; nt++) {
                float p0 = __expf(s[nt][2 * r] - mx);
                float p1 = __expf(s[nt][2 * r + 1] - mx);
                s[nt][2 * r] = p0;
                s[nt][2 * r + 1] = p1;
                sumv += p0 + p1;
            }
            sumv += __shfl_xor_sync(0xffffffffu, sumv, 1);
            sumv += __shfl_xor_sync(0xffffffffu, sumv, 2);
            float sc = __expf(mrun[r] - mx);
            lrun[r] = lrun[r] * sc + sumv;
            mrun[r] = mx;
#pragma unroll
            for (int nt = 0; nt < 8; nt++) {
                o[nt][2 * r] *= sc;
                o[nt][2 * r + 1] *= sc;
            }
        }

        // Write P (tf32) to Ps — warp-private rows
        {
            const int r0 = warp * 16 + gid;
            const int r1 = r0 + 8;
            const int sw0 = (r0 & 7) << 2;
            const int sw1 = (r1 & 7) << 2;
#pragma unroll
            for (int nt = 0; nt < 8; nt++) {
                int colb = nt * 8 + 2 * tig;
                Ps[r0][colb ^ sw0] = f2tf(s[nt][0]);
                Ps[r0][(colb + 1) ^ sw0] = f2tf(s[nt][1]);
                Ps[r1][colb ^ sw1] = f2tf(s[nt][2]);
                Ps[r1][(colb + 1) ^ sw1] = f2tf(s[nt][3]);
            }
        }
        __syncthreads();   // V visible + P visible

        // O += P @ V   (B[k=key][n=d] = V[key][d])
        {
            const int r0 = warp * 16 + gid;
            const int r1 = r0 + 8;
            const int sw0 = (r0 & 7) << 2;
            const int sw1 = (r1 & 7) << 2;
#pragma unroll
            for (int ks = 0; ks < 8; ks++) {
                unsigned af[4];
                int d0 = ks * 8 + tig;
                af[0] = Ps[r0][d0 ^ sw0];
                af[1] = Ps[r1][d0 ^ sw1];
                af[2] = Ps[r0][(d0 + 4) ^ sw0];
                af[3] = Ps[r1][(d0 + 4) ^ sw1];
                const int key0 = ks * 8 + tig;
#pragma unroll
                for (int nt = 0; nt < 8; nt++) {
                    int dd = nt * 8 + gid;
                    unsigned bf[2];
                    bf[0] = KVs[key0][kvswz(key0, dd)];
                    bf[1] = KVs[key0 + 4][kvswz(key0 + 4, dd)];
                    mma_tf32(o[nt], af, bf);
                }
            }
        }
        __syncthreads();   // before next tile overwrites KVs/Ps
    }

    // Epilogue: normalize and store
#pragma unroll
    for (int r = 0; r < 2; r++) {
        float inv = 1.0f / lrun[r];
        int row = q0 + warp * 16 + gid + 8 * r;
#pragma unroll
        for (int nt = 0; nt < 8; nt++) {
            int col = nt * 8 + 2 * tig;
            float2 v = make_float2(o[nt][2 * r] * inv, o[nt][2 * r + 1] * inv);
            *(float2*)&O[base + (size_t)row * Dm + col] = v;
        }
    }
}

// ---------------------------------------------------------------------------
// Residual + LayerNorm: out = LN(x + proj) * gamma + beta
// ---------------------------------------------------------------------------
__global__ __launch_bounds__(256)
void resid_ln(const float* __restrict__ x, const float* __restrict__ proj,
              const float* __restrict__ gamma, const float* __restrict__ beta,
              float* __restrict__ out) {
    __shared__ float red1[8];
    __shared__ float red2[8];
    const int row = blockIdx.x;
    const int t = threadIdx.x;
    const float* xr = x + (size_t)row * Dm;
    const float* pr = proj + (size_t)row * Dm;
    float* outr = out + (size_t)row * Dm;

    float v[4];
    float s = 0.f;
#pragma unroll
    for (int i = 0; i < 4; i++) {
        int c = t + 256 * i;
        v[i] = xr[c] + pr[c];
        s += v[i];
    }
#pragma unroll
    for (int off = 16; off > 0; off >>= 1) s += __shfl_xor_sync(~0u, s, off);
    if ((t & 31) == 0) red1[t >> 5] = s;
    __syncthreads();
    float mu = 0.f;
#pragma unroll
    for (int i = 0; i < 8; i++) mu += red1[i];
    mu *= (1.0f / Dm);

    float vs = 0.f;
#pragma unroll
    for (int i = 0; i < 4; i++) {
        float d = v[i] - mu;
        vs += d * d;
    }
#pragma unroll
    for (int off = 16; off > 0; off >>= 1) vs += __shfl_xor_sync(~0u, vs, off);
    if ((t & 31) == 0) red2[t >> 5] = vs;
    __syncthreads();
    float var = 0.f;
#pragma unroll
    for (int i = 0; i < 8; i++) var += red2[i];
    var *= (1.0f / Dm);
    float rstd = rsqrtf(var + EPSLN);

#pragma unroll
    for (int i = 0; i < 4; i++) {
        int c = t + 256 * i;
        outr[c] = (v[i] - mu) * rstd * gamma[c] + beta[c];
    }
}

// ---------------------------------------------------------------------------
extern "C" void kernel_launch(void* const* d_in, const int* in_sizes, int n_in,
                              void* d_out, int out_size) {
    const float* x     = (const float*)d_in[0];
    const float* Wq    = (const float*)d_in[1];
    const float* bq    = (const float*)d_in[2];
    const float* Wk    = (const float*)d_in[3];
    const float* bk    = (const float*)d_in[4];
    const float* Wv    = (const float*)d_in[5];
    const float* bv    = (const float*)d_in[6];
    const float* Wo    = (const float*)d_in[7];
    const float* bo    = (const float*)d_in[8];
    const float* gamma = (const float*)d_in[9];
    const float* beta  = (const float*)d_in[10];
    float* out = (float*)d_out;

    float *q, *k, *v, *attn, *proj;
    cudaGetSymbolAddress((void**)&q,    g_q);
    cudaGetSymbolAddress((void**)&k,    g_k);
    cudaGetSymbolAddress((void**)&v,    g_v);
    cudaGetSymbolAddress((void**)&attn, g_attn);
    cudaGetSymbolAddress((void**)&proj, g_proj);

    dim3 ggrid(Dm / 128, Mrows / 128);   // (8, 64)
    gemm_tc<<<ggrid, 256>>>(x, Wq, bq, q);
    gemm_tc<<<ggrid, 256>>>(x, Wk, bk, k);
    gemm_tc<<<ggrid, 256>>>(x, Wv, bv, v);

    dim3 agrid(Lz / 64, Hh, Bz);         // (32, 16, 4)
    attn_tc<<<agrid, 128>>>(q, k, v, attn);

    gemm_tc<<<ggrid, 256>>>(attn, Wo, bo, proj);

    resid_ln<<<Mrows, 256>>>(x, proj, gamma, beta, out);
}

// round 7
// speedup vs baseline: 4.4771x; 1.5457x over previous
#include <cuda_runtime.h>
#include <math.h>

// Problem constants
#define Bz 4
#define Lz 2048
#define Dm 1024
#define Hh 16
#define HD 64
#define Mrows (Bz*Lz)   // 8192
#define EPSLN 1e-5f

// Scratch (static device globals — allocation-free)
__device__ float g_q[(size_t)Mrows * Dm];
__device__ float g_k[(size_t)Mrows * Dm];
__device__ float g_v[(size_t)Mrows * Dm];
__device__ float g_attn[(size_t)Mrows * Dm];
__device__ float g_proj[(size_t)Mrows * Dm];

// ---------------------------------------------------------------------------
// Helpers: cp.async + tf32 mma (fp32 bits fed directly; HW truncates mantissa)
// ---------------------------------------------------------------------------
__device__ __forceinline__ unsigned su32(const void* p) {
    return (unsigned)__cvta_generic_to_shared(p);
}
#define CPA(dst, src) asm volatile("cp.async.cg.shared.global [%0], [%1], 16;\n" :: "r"(dst), "l"(src))
#define CPC() asm volatile("cp.async.commit_group;\n" ::: "memory")
template <int N> __device__ __forceinline__ void cpw() {
    asm volatile("cp.async.wait_group %0;\n" :: "n"(N) : "memory");
}
#define U(x) __float_as_uint(x)

__device__ __forceinline__ void mma_tf32(float c[4], const unsigned a[4],
                                         const unsigned b[2]) {
    asm volatile(
        "mma.sync.aligned.m16n8k8.row.col.f32.tf32.tf32.f32 "
        "{%0,%1,%2,%3},{%4,%5,%6,%7},{%8,%9},{%0,%1,%2,%3};"
        : "+f"(c[0]), "+f"(c[1]), "+f"(c[2]), "+f"(c[3])
        : "r"(a[0]), "r"(a[1]), "r"(a[2]), "r"(a[3]), "r"(b[0]), "r"(b[1]));
}

// ---------------------------------------------------------------------------
// GEMM: C[M,N] = A[M,K] @ W[K,N] + bias[N]   (M=8192, N=K=1024)
// CTA 128x128, BK=32, 8 warps (2x4 of 64x32), cp.async 2-stage pipeline.
// A smem [m][k], chunk swizzle: chunk' = kchunk ^ (m&7)   (16B chunks)
// B smem [k][n], chunk swizzle: chunk' = nchunk ^ ((k&3)<<1)
// Both fragment LDS patterns verified conflict-free (32 distinct banks).
// ---------------------------------------------------------------------------
__device__ __forceinline__ void gemm_issue(float* As, float* Bs,
                                           const float* __restrict__ A,
                                           const float* __restrict__ W,
                                           int m0, int n0, int k0) {
    const int tid = threadIdx.x;
#pragma unroll
    for (int it = 0; it < 4; it++) {
        int f = tid + it * 256;          // 0..1023 chunks of A tile
        int m = f >> 3;                  // 0..127
        int kc = f & 7;                  // 0..7
        CPA(su32(As + m * 32 + ((kc ^ (m & 7)) << 2)),
            A + (size_t)(m0 + m) * Dm + k0 + kc * 4);
    }
#pragma unroll
    for (int it = 0; it < 4; it++) {
        int f = tid + it * 256;          // 0..1023 chunks of B tile
        int k = f >> 5;                  // 0..31
        int nc = f & 31;                 // 0..31
        CPA(su32(Bs + k * 128 + ((nc ^ ((k & 3) << 1)) << 2)),
            W + (size_t)(k0 + k) * Dm + n0 + nc * 4);
    }
}

__device__ __forceinline__ void gemm_body(const float* __restrict__ A,
                                          const float* __restrict__ W,
                                          const float* __restrict__ bias,
                                          float* __restrict__ C) {
    extern __shared__ float sg[];
    float* As = sg;            // 2 stages x 128x32
    float* Bs = sg + 8192;     // 2 stages x 32x128

    const int tid = threadIdx.x;
    const int lane = tid & 31;
    const int warp = tid >> 5;
    const int gid = lane >> 2;
    const int tig = lane & 3;
    const int wm = (warp >> 2) * 64;
    const int wn = (warp & 3) * 32;
    const int m0 = blockIdx.y * 128;
    const int n0 = blockIdx.x * 128;

    float c[4][4][4];
#pragma unroll
    for (int mt = 0; mt < 4; mt++)
#pragma unroll
        for (int nt = 0; nt < 4; nt++)
#pragma unroll
            for (int r = 0; r < 4; r++) c[mt][nt][r] = 0.f;

    gemm_issue(As, Bs, A, W, m0, n0, 0);
    CPC();

    const int KT = Dm / 32;
    for (int kt = 0; kt < KT; kt++) {
        cpw<0>();
        __syncthreads();
        if (kt + 1 < KT) {
            gemm_issue(As + ((kt + 1) & 1) * 4096, Bs + ((kt + 1) & 1) * 4096,
                       A, W, m0, n0, (kt + 1) * 32);
            CPC();
        }
        const float* Ax = As + (kt & 1) * 4096;
        const float* Bx = Bs + (kt & 1) * 4096;

#pragma unroll
        for (int ks = 0; ks < 4; ks++) {
            const int kA = ks * 8 + tig;
            unsigned af[4][4], bf[4][2];
#pragma unroll
            for (int mt = 0; mt < 4; mt++) {
                int m = wm + 16 * mt + gid;
                int c0 = ((2 * ks) ^ (m & 7)) << 2;
                int c1 = ((2 * ks + 1) ^ (m & 7)) << 2;
                af[mt][0] = U(Ax[m * 32 + c0 + tig]);
                af[mt][1] = U(Ax[(m + 8) * 32 + c0 + tig]);   // (m+8)&7 == m&7
                af[mt][2] = U(Ax[m * 32 + c1 + tig]);
                af[mt][3] = U(Ax[(m + 8) * 32 + c1 + tig]);
            }
#pragma unroll
            for (int nt = 0; nt < 4; nt++) {
                int n = wn + 8 * nt + gid;
                int cc = (((n >> 2) ^ (tig << 1)) << 2) + (n & 3);
                bf[nt][0] = U(Bx[kA * 128 + cc]);
                bf[nt][1] = U(Bx[(kA + 4) * 128 + cc]);
            }
#pragma unroll
            for (int mt = 0; mt < 4; mt++)
#pragma unroll
                for (int nt = 0; nt < 4; nt++)
                    mma_tf32(c[mt][nt], af[mt], bf[nt]);
        }
        // no trailing sync: next iteration's cpw+sync orders compute before
        // the overwrite of this stage (issued at kt+1 targets stage (kt+2)&1)
    }

#pragma unroll
    for (int mt = 0; mt < 4; mt++) {
        int m = m0 + wm + 16 * mt + gid;
#pragma unroll
        for (int nt = 0; nt < 4; nt++) {
            int n = n0 + wn + 8 * nt + 2 * tig;
            float2 bb = *(const float2*)&bias[n];
            *(float2*)&C[(size_t)m * Dm + n] =
                make_float2(c[mt][nt][0] + bb.x, c[mt][nt][1] + bb.y);
            *(float2*)&C[(size_t)(m + 8) * Dm + n] =
                make_float2(c[mt][nt][2] + bb.x, c[mt][nt][3] + bb.y);
        }
    }
}

__global__ __launch_bounds__(256, 2)
void gemm_qkv(const float* __restrict__ x,
              const float* __restrict__ Wq, const float* __restrict__ bq,
              const float* __restrict__ Wk, const float* __restrict__ bk,
              const float* __restrict__ Wv, const float* __restrict__ bv,
              float* __restrict__ q, float* __restrict__ k, float* __restrict__ v) {
    const int z = blockIdx.z;
    const float* W = (z == 0) ? Wq : ((z == 1) ? Wk : Wv);
    const float* bb = (z == 0) ? bq : ((z == 1) ? bk : bv);
    float* C = (z == 0) ? q : ((z == 1) ? k : v);
    gemm_body(x, W, bb, C);
}

__global__ __launch_bounds__(256, 2)
void gemm_one(const float* __restrict__ A, const float* __restrict__ W,
              const float* __restrict__ b, float* __restrict__ C) {
    gemm_body(A, W, b, C);
}

// ---------------------------------------------------------------------------
// Flash attention, tensor cores, cp.async double-buffered K/V.
// One CTA per (b, h, 128-q-row tile): 8 warps, each owns 16 query rows.
// KV swizzle (16B chunks): chunk' = chunk ^ SWZ3(row) — conflict-free for
// BOTH S-phase (K^T) and PV-phase (V) fragment patterns (verified).
// Ps (Q staging / P tiles): chunk' = chunk ^ (row&7).
// ---------------------------------------------------------------------------
#define SWZ3(r) (((((r) >> 2) & 1)) | ((((r) & 1)) << 1) | (((((r) >> 1) & 1)) << 2))

__device__ __forceinline__ void issue_kv(float* buf, const float* __restrict__ src) {
    const int tid = threadIdx.x;
#pragma unroll
    for (int it = 0; it < 4; it++) {
        int f = tid + it * 256;          // 0..1023 chunks (64x16)
        int r = f >> 4;                  // 0..63
        int cc = f & 15;                 // 0..15
        CPA(su32(buf + r * 64 + ((cc ^ SWZ3(r)) << 2)),
            src + (size_t)r * Dm + cc * 4);
    }
}

__global__ __launch_bounds__(256, 1)
void attn_tc(const float* __restrict__ Q, const float* __restrict__ K,
             const float* __restrict__ V, float* __restrict__ O) {
    extern __shared__ float sa[];
    float* Kb = sa;            // 64x64
    float* Vb = sa + 4096;     // 64x64
    float* Ps = sa + 8192;     // 128x64 (Q staging, then P tiles)

    const int tid = threadIdx.x;
    const int lane = tid & 31;
    const int warp = tid >> 5;
    const int gid = lane >> 2;
    const int tig = lane & 3;
    const int q0 = blockIdx.x * 128;
    const int h = blockIdx.y;
    const int b = blockIdx.z;
    const size_t base = (size_t)b * Lz * Dm + (size_t)h * HD;

    // Prologue: async-load Q (128x64), K(0), V(0)
#pragma unroll
    for (int it = 0; it < 8; it++) {
        int f = tid + it * 256;          // 0..2047 chunks
        int r = f >> 4;                  // 0..127
        int cc = f & 15;
        CPA(su32(Ps + r * 64 + ((cc ^ (r & 7)) << 2)),
            Q + base + (size_t)(q0 + r) * Dm + cc * 4);
    }
    CPC();
    issue_kv(Kb, K + base); CPC();
    issue_kv(Vb, V + base); CPC();

    cpw<2>();           // Q landed (K0/V0 may be in flight)
    __syncthreads();

    // Q fragments -> registers, scaled by 1/sqrt(HD)=0.125
    const int r0 = warp * 16 + gid;
    const int r1 = r0 + 8;
    const int sw0 = r0 & 7;
    const int sw1 = r1 & 7;
    unsigned qf[8][4];
#pragma unroll
    for (int ks = 0; ks < 8; ks++) {
        qf[ks][0] = U(0.125f * Ps[r0 * 64 + (((2 * ks) ^ sw0) << 2) + tig]);
        qf[ks][1] = U(0.125f * Ps[r1 * 64 + (((2 * ks) ^ sw1) << 2) + tig]);
        qf[ks][2] = U(0.125f * Ps[r0 * 64 + (((2 * ks + 1) ^ sw0) << 2) + tig]);
        qf[ks][3] = U(0.125f * Ps[r1 * 64 + (((2 * ks + 1) ^ sw1) << 2) + tig]);
    }

    float o[8][4];
#pragma unroll
    for (int nt = 0; nt < 8; nt++)
#pragma unroll
        for (int r = 0; r < 4; r++) o[nt][r] = 0.f;
    float mrun[2] = {-1e30f, -1e30f};
    float lrun[2] = {0.f, 0.f};

    const int NT = Lz / 64;
    for (int t = 0; t < NT; t++) {
        cpw<1>();               // K(t) ready (V(t) may be outstanding)
        __syncthreads();        // also orders qf reads (t=0) before P writes

        // S = Q @ K^T
        float s[8][4];
#pragma unroll
        for (int nt = 0; nt < 8; nt++)
#pragma unroll
            for (int r = 0; r < 4; r++) s[nt][r] = 0.f;
#pragma unroll
        for (int ks = 0; ks < 8; ks++) {
#pragma unroll
            for (int nt = 0; nt < 8; nt++) {
                int key = nt * 8 + gid;
                int sw = SWZ3(key);
                unsigned bf[2];
                bf[0] = U(Kb[key * 64 + (((2 * ks) ^ sw) << 2) + tig]);
                bf[1] = U(Kb[key * 64 + (((2 * ks + 1) ^ sw) << 2) + tig]);
                mma_tf32(s[nt], qf[ks], bf);
            }
        }
        __syncthreads();        // all warps done reading Kb
        if (t + 1 < NT) { issue_kv(Kb, K + base + (size_t)(t + 1) * 64 * Dm); CPC(); }

        // Online softmax (registers; row stats via quad shuffles)
#pragma unroll
        for (int r = 0; r < 2; r++) {
            float mx = mrun[r];
#pragma unroll
            for (int nt = 0; nt < 8; nt++) {
                mx = fmaxf(mx, s[nt][2 * r]);
                mx = fmaxf(mx, s[nt][2 * r + 1]);
            }
            mx = fmaxf(mx, __shfl_xor_sync(0xffffffffu, mx, 1));
            mx = fmaxf(mx, __shfl_xor_sync(0xffffffffu, mx, 2));
            float sumv = 0.f;
#pragma unroll
            for (int nt = 0; nt < 8; nt++) {
                float p0 = __expf(s[nt][2 * r] - mx);
                float p1 = __expf(s[nt][2 * r + 1] - mx);
                s[nt][2 * r] = p0;
                s[nt][2 * r + 1] = p1;
                sumv += p0 + p1;
            }
            sumv += __shfl_xor_sync(0xffffffffu, sumv, 1);
            sumv += __shfl_xor_sync(0xffffffffu, sumv, 2);
            float sc = __expf(mrun[r] - mx);
            lrun[r] = lrun[r] * sc + sumv;
            mrun[r] = mx;
#pragma unroll
            for (int nt = 0; nt < 8; nt++) {
                o[nt][2 * r] *= sc;
                o[nt][2 * r + 1] *= sc;
            }
        }

        if (t + 1 < NT) cpw<1>(); else cpw<0>();   // V(t) ready
        __syncthreads();

        // Write P (raw fp32 bits; mma truncates) — warp-private rows
#pragma unroll
        for (int nt = 0; nt < 8; nt++) {
            int cb = nt * 8 + 2 * tig;
            int ch = cb >> 2, wi = cb & 3;
            *(float2*)&Ps[r0 * 64 + ((ch ^ sw0) << 2) + wi] =
                make_float2(s[nt][0], s[nt][1]);
            *(float2*)&Ps[r1 * 64 + ((ch ^ sw1) << 2) + wi] =
                make_float2(s[nt][2], s[nt][3]);
        }
        __syncthreads();        // P visible

        // O += P @ V
#pragma unroll
        for (int ks = 0; ks < 8; ks++) {
            unsigned af[4];
            af[0] = U(Ps[r0 * 64 + (((2 * ks) ^ sw0) << 2) + tig]);
            af[1] = U(Ps[r1 * 64 + (((2 * ks) ^ sw1) << 2) + tig]);
            af[2] = U(Ps[r0 * 64 + (((2 * ks + 1) ^ sw0) << 2) + tig]);
            af[3] = U(Ps[r1 * 64 + (((2 * ks + 1) ^ sw1) << 2) + tig]);
            int key0 = ks * 8 + tig;
            int swk0 = SWZ3(key0), swk1 = SWZ3(key0 + 4);
#pragma unroll
            for (int nt = 0; nt < 8; nt++) {
                int dd = nt * 8 + gid;
                int ch = dd >> 2, wi = dd & 3;
                unsigned bf[2];
                bf[0] = U(Vb[key0 * 64 + ((ch ^ swk0) << 2) + wi]);
                bf[1] = U(Vb[(key0 + 4) * 64 + ((ch ^ swk1) << 2) + wi]);
                mma_tf32(o[nt], af, bf);
            }
        }
        __syncthreads();        // done reading Vb + Ps
        if (t + 1 < NT) { issue_kv(Vb, V + base + (size_t)(t + 1) * 64 * Dm); CPC(); }
    }

    // Epilogue: normalize + store
#pragma unroll
    for (int r = 0; r < 2; r++) {
        float inv = 1.0f / lrun[r];
        int row = q0 + warp * 16 + gid + 8 * r;
#pragma unroll
        for (int nt = 0; nt < 8; nt++) {
            int col = nt * 8 + 2 * tig;
            *(float2*)&O[base + (size_t)row * Dm + col] =
                make_float2(o[nt][2 * r] * inv, o[nt][2 * r + 1] * inv);
        }
    }
}

// ---------------------------------------------------------------------------
// Residual + LayerNorm
// ---------------------------------------------------------------------------
__global__ __launch_bounds__(256)
void resid_ln(const float* __restrict__ x, const float* __restrict__ proj,
              const float* __restrict__ gamma, const float* __restrict__ beta,
              float* __restrict__ out) {
    __shared__ float red1[8];
    __shared__ float red2[8];
    const int row = blockIdx.x;
    const int t = threadIdx.x;
    const float* xr = x + (size_t)row * Dm;
    const float* pr = proj + (size_t)row * Dm;
    float* outr = out + (size_t)row * Dm;

    float v[4];
    float s = 0.f;
#pragma unroll
    for (int i = 0; i < 4; i++) {
        int c = t + 256 * i;
        v[i] = xr[c] + pr[c];
        s += v[i];
    }
#pragma unroll
    for (int off = 16; off > 0; off >>= 1) s += __shfl_xor_sync(~0u, s, off);
    if ((t & 31) == 0) red1[t >> 5] = s;
    __syncthreads();
    float mu = 0.f;
#pragma unroll
    for (int i = 0; i < 8; i++) mu += red1[i];
    mu *= (1.0f / Dm);

    float vs = 0.f;
#pragma unroll
    for (int i = 0; i < 4; i++) {
        float d = v[i] - mu;
        vs += d * d;
    }
#pragma unroll
    for (int off = 16; off > 0; off >>= 1) vs += __shfl_xor_sync(~0u, vs, off);
    if ((t & 31) == 0) red2[t >> 5] = vs;
    __syncthreads();
    float var = 0.f;
#pragma unroll
    for (int i = 0; i < 8; i++) var += red2[i];
    var *= (1.0f / Dm);
    float rstd = rsqrtf(var + EPSLN);

#pragma unroll
    for (int i = 0; i < 4; i++) {
        int c = t + 256 * i;
        outr[c] = (v[i] - mu) * rstd * gamma[c] + beta[c];
    }
}

// ---------------------------------------------------------------------------
extern "C" void kernel_launch(void* const* d_in, const int* in_sizes, int n_in,
                              void* d_out, int out_size) {
    const float* x     = (const float*)d_in[0];
    const float* Wq    = (const float*)d_in[1];
    const float* bq    = (const float*)d_in[2];
    const float* Wk    = (const float*)d_in[3];
    const float* bk    = (const float*)d_in[4];
    const float* Wv    = (const float*)d_in[5];
    const float* bv    = (const float*)d_in[6];
    const float* Wo    = (const float*)d_in[7];
    const float* bo    = (const float*)d_in[8];
    const float* gamma = (const float*)d_in[9];
    const float* beta  = (const float*)d_in[10];
    float* out = (float*)d_out;

    float *q, *k, *v, *attn, *proj;
    cudaGetSymbolAddress((void**)&q,    g_q);
    cudaGetSymbolAddress((void**)&k,    g_k);
    cudaGetSymbolAddress((void**)&v,    g_v);
    cudaGetSymbolAddress((void**)&attn, g_attn);
    cudaGetSymbolAddress((void**)&proj, g_proj);

    const int gemm_smem = 16384 * 4;   // 64 KB (2-stage A+B)
    const int attn_smem = 16384 * 4;   // 64 KB (K + V + Ps)
    cudaFuncSetAttribute(gemm_qkv, cudaFuncAttributeMaxDynamicSharedMemorySize, gemm_smem);
    cudaFuncSetAttribute(gemm_one, cudaFuncAttributeMaxDynamicSharedMemorySize, gemm_smem);
    cudaFuncSetAttribute(attn_tc,  cudaFuncAttributeMaxDynamicSharedMemorySize, attn_smem);

    dim3 qkvgrid(Dm / 128, Mrows / 128, 3);   // (8, 64, 3)
    gemm_qkv<<<qkvgrid, 256, gemm_smem>>>(x, Wq, bq, Wk, bk, Wv, bv, q, k, v);

    dim3 agrid(Lz / 128, Hh, Bz);             // (16, 16, 4)
    attn_tc<<<agrid, 256, attn_smem>>>(q, k, v, attn);

    dim3 ogrid(Dm / 128, Mrows / 128);        // (8, 64)
    gemm_one<<<ogrid, 256, gemm_smem>>>(attn, Wo, bo, proj);

    resid_ln<<<Mrows, 256>>>(x, proj, gamma, beta, out);
}